// round 2
// baseline (speedup 1.0000x reference)
#include <cuda_runtime.h>
#include <math.h>

#define B_    32
#define L_    512
#define H_    256
#define E_    300
#define NH    8
#define HD    32
#define NITER 6
#define L1    513            // L+1 (relay + nodes)
#define M1    (B_*L_)        // 16384
#define M2    (B_*L1)        // 16416

// ---------------- scratch (static __device__, no allocation) ----------------
__device__ float d_e    [M1*E_];
__device__ float d_nodes[M1*H_];
__device__ float d_nln  [M1*H_];
__device__ float d_q    [M1*H_];
__device__ float d_k    [M1*H_];
__device__ float d_att  [M1*H_];
__device__ float d_y    [M2*H_];
__device__ float d_k2   [M2*H_];
__device__ float d_v2   [M2*H_];
__device__ float d_relay[B_*H_];
__device__ float d_ak   [B_*H_];
__device__ float d_av   [B_*H_];
__device__ float d_q2   [B_*H_];
__device__ float d_att2 [B_*H_];

// ---------------- generic tiled GEMM: C[M,256] = A[M,K] @ W[K,256] ----------
// EPI 0: C = acc + bias
// EPI 1: C = C + leaky_relu(acc + bias)         (residual into nodes)
// EPI 2: C = acc + bias + pos[m % 512]          (embedding epilogue)
#define GBM 128
#define GBN 64
#define GBK 16
#define GN  256

template<int EPI>
__global__ void __launch_bounds__(256)
gemm256(const float* __restrict__ A, const float* __restrict__ W,
        const float* __restrict__ bias, float* __restrict__ C,
        int M, int K, const float* __restrict__ pos)
{
    __shared__ float As[GBK][GBM];
    __shared__ float Bs[GBK][GBN];

    const int tid = threadIdx.x;
    const int m0 = blockIdx.x * GBM;
    const int n0 = blockIdx.y * GBN;

    const int arow = tid >> 2;           // 0..63
    const int acol = (tid & 3) * 4;      // 0,4,8,12
    const int brow = tid >> 4;           // 0..15
    const int bcol = (tid & 15) * 4;     // 0..60
    const int ty = tid >> 4;             // 0..15  (rows ty*8..+7)
    const int tx = tid & 15;             // 0..15  (cols tx*4..+3)

    float acc[8][4];
#pragma unroll
    for (int i = 0; i < 8; i++)
#pragma unroll
        for (int j = 0; j < 4; j++) acc[i][j] = 0.f;

    for (int kb = 0; kb < K; kb += GBK) {
        // --- load A tile (128 x 16), transposed into As[k][m] ---
#pragma unroll
        for (int p = 0; p < 2; p++) {
            int r  = arow + p * 64;
            int gm = m0 + r;
            float4 v = make_float4(0.f, 0.f, 0.f, 0.f);
            if (gm < M) {
                int gk = kb + acol;
                if (gk + 3 < K) {
                    v = *(const float4*)(A + (size_t)gm * K + gk);
                } else {
                    float tmp[4] = {0.f, 0.f, 0.f, 0.f};
                    for (int c = 0; c < 4; c++)
                        if (gk + c < K) tmp[c] = A[(size_t)gm * K + gk + c];
                    v = make_float4(tmp[0], tmp[1], tmp[2], tmp[3]);
                }
            }
            As[acol + 0][r] = v.x;
            As[acol + 1][r] = v.y;
            As[acol + 2][r] = v.z;
            As[acol + 3][r] = v.w;
        }
        // --- load B tile (16 x 64) ---
        {
            int gk = kb + brow;
            float4 v = make_float4(0.f, 0.f, 0.f, 0.f);
            if (gk < K) v = *(const float4*)(W + (size_t)gk * GN + n0 + bcol);
            Bs[brow][bcol + 0] = v.x;
            Bs[brow][bcol + 1] = v.y;
            Bs[brow][bcol + 2] = v.z;
            Bs[brow][bcol + 3] = v.w;
        }
        __syncthreads();
#pragma unroll
        for (int kk = 0; kk < GBK; kk++) {
            const float* ap = &As[kk][ty * 8];
            float4 a0 = *(const float4*)ap;
            float4 a1 = *(const float4*)(ap + 4);
            float4 bb = *(const float4*)&Bs[kk][tx * 4];
            float av8[8] = {a0.x, a0.y, a0.z, a0.w, a1.x, a1.y, a1.z, a1.w};
            float bv4[4] = {bb.x, bb.y, bb.z, bb.w};
#pragma unroll
            for (int i = 0; i < 8; i++)
#pragma unroll
                for (int j = 0; j < 4; j++)
                    acc[i][j] += av8[i] * bv4[j];
        }
        __syncthreads();
    }

    // --- epilogue ---
    float4 bv = *(const float4*)(bias + n0 + tx * 4);
#pragma unroll
    for (int i = 0; i < 8; i++) {
        int gm = m0 + ty * 8 + i;
        if (gm >= M) continue;
        float r0 = acc[i][0] + bv.x;
        float r1 = acc[i][1] + bv.y;
        float r2 = acc[i][2] + bv.z;
        float r3 = acc[i][3] + bv.w;
        float* cp = C + (size_t)gm * GN + n0 + tx * 4;
        if (EPI == 2) {
            const float4 p = *(const float4*)(pos + (size_t)(gm & (L_ - 1)) * GN + n0 + tx * 4);
            r0 += p.x; r1 += p.y; r2 += p.z; r3 += p.w;
            *(float4*)cp = make_float4(r0, r1, r2, r3);
        } else if (EPI == 1) {
            r0 = r0 > 0.f ? r0 : 0.01f * r0;
            r1 = r1 > 0.f ? r1 : 0.01f * r1;
            r2 = r2 > 0.f ? r2 : 0.01f * r2;
            r3 = r3 > 0.f ? r3 : 0.01f * r3;
            float4 old = *(const float4*)cp;
            *(float4*)cp = make_float4(old.x + r0, old.y + r1, old.z + r2, old.w + r3);
        } else {
            *(float4*)cp = make_float4(r0, r1, r2, r3);
        }
    }
}

// ---------------- embedding gather ----------------
__global__ void gather_emb(const int* __restrict__ data, const float* __restrict__ emb,
                           float* __restrict__ e)
{
    size_t i = (size_t)blockIdx.x * 256 + threadIdx.x;
    if (i >= (size_t)M1 * E_) return;
    int row = (int)(i / E_);
    int c   = (int)(i % E_);
    e[i] = emb[(size_t)data[row] * E_ + c];
}

// ---------------- relay init: mean over L ----------------
__global__ void mean_k(const float* __restrict__ x, float* __restrict__ relay)
{
    int b = blockIdx.x, d = threadIdx.x;
    float acc = 0.f;
    for (int l = 0; l < L_; l++)
        acc += x[((size_t)(b * L_ + l)) * H_ + d];
    relay[b * H_ + d] = acc * (1.f / L_);
}

// ---------------- layernorm, one token per block ----------------
__global__ void ln_k(const float* __restrict__ x, const float* __restrict__ g,
                     const float* __restrict__ b, float* __restrict__ y)
{
    __shared__ float red[256];
    int tok = blockIdx.x, t = threadIdx.x;
    float v = x[(size_t)tok * H_ + t];
    red[t] = v;
    __syncthreads();
    for (int s = 128; s > 0; s >>= 1) { if (t < s) red[t] += red[t + s]; __syncthreads(); }
    float mu = red[0] * (1.f / H_);
    __syncthreads();
    float dv = v - mu;
    red[t] = dv * dv;
    __syncthreads();
    for (int s = 128; s > 0; s >>= 1) { if (t < s) red[t] += red[t + s]; __syncthreads(); }
    float var = red[0] * (1.f / H_);
    y[(size_t)tok * H_ + t] = g[t] * dv * rsqrtf(var + 1e-5f) + b[t];
}

// ---------------- small row GEMM (M small): C[M,256]=A[M,256]@W + b ----------
__global__ void small_proj(const float* __restrict__ A, const float* __restrict__ W,
                           const float* __restrict__ bias, float* __restrict__ C,
                           int leaky)
{
    __shared__ float sa[H_];
    int m = blockIdx.x, n = threadIdx.x;
    sa[n] = A[(size_t)m * H_ + n];
    __syncthreads();
    float acc = 0.f;
#pragma unroll 8
    for (int k = 0; k < H_; k++) acc += sa[k] * W[(size_t)k * H_ + n];
    acc += bias[n];
    if (leaky) acc = acc > 0.f ? acc : 0.01f * acc;
    C[(size_t)m * H_ + n] = acc;
}

// ---------------- ring attention (msa1): 4 keys/token, values==keys bug ------
__global__ void msa1_attn(const float* __restrict__ q, const float* __restrict__ k,
                          const float* __restrict__ ak, const float* __restrict__ av,
                          float* __restrict__ att)
{
    int token = blockIdx.x;
    int b = token >> 9;       // /512
    int l = token & 511;
    int h = threadIdx.x >> 5;
    int d = threadIdx.x & 31;
    int off = h * HD + d;

    float qd  = q[(size_t)token * H_ + off];
    float akd = ak[b * H_ + off];
    float avd = av[b * H_ + off];
    float km1 = (l > 0)      ? k[(size_t)(token - 1) * H_ + off] : 0.f;
    float k0v =                k[(size_t)token * H_ + off];
    float kp1 = (l < L_ - 1) ? k[(size_t)(token + 1) * H_ + off] : 0.f;

    float s0 = qd * akd, s1 = qd * km1, s2 = qd * k0v, s3 = qd * kp1;
#pragma unroll
    for (int o = 16; o; o >>= 1) {
        s0 += __shfl_xor_sync(0xffffffffu, s0, o);
        s1 += __shfl_xor_sync(0xffffffffu, s1, o);
        s2 += __shfl_xor_sync(0xffffffffu, s2, o);
        s3 += __shfl_xor_sync(0xffffffffu, s3, o);
    }
    const float sc = 0.17677669529663687f;   // 1/sqrt(32)
    s0 *= sc; s1 *= sc; s2 *= sc; s3 *= sc;
    float mx = fmaxf(fmaxf(s0, s1), fmaxf(s2, s3));
    float e0 = expf(s0 - mx), e1 = expf(s1 - mx), e2 = expf(s2 - mx), e3 = expf(s3 - mx);
    float inv = 1.f / (e0 + e1 + e2 + e3);
    // values: relay value + WINDOW KEY vectors (faithful to source bug)
    att[(size_t)token * H_ + off] = (e0 * avd + e1 * km1 + e2 * k0v + e3 * kp1) * inv;
}

// ---------------- build y = [relay; nodes], then mask nodes ------------------
__global__ void ybuild(const float* __restrict__ relay, float* __restrict__ nodes,
                       float* __restrict__ y, const int* __restrict__ data)
{
    int row = blockIdx.x;         // 0 .. M2-1
    int d = threadIdx.x;
    int b = row / L1;
    int j = row - b * L1;
    if (j == 0) {
        y[(size_t)row * H_ + d] = relay[b * H_ + d];
    } else {
        int tok = b * L_ + (j - 1);
        float v = nodes[(size_t)tok * H_ + d];
        y[(size_t)row * H_ + d] = v;
        if (data[tok] == 1) nodes[(size_t)tok * H_ + d] = 0.f;   // mask AFTER y is built
    }
}

// ---------------- relay attention (msa2): softmax over 513 keys --------------
__global__ void msa2_attn(const float* __restrict__ q2, const float* __restrict__ k2,
                          const float* __restrict__ v2, float* __restrict__ att2)
{
    __shared__ float sq[HD];
    __shared__ float scs[L1];
    __shared__ float red[256];
    int bh = blockIdx.x;
    int b = bh >> 3, h = bh & 7;
    int t = threadIdx.x;

    if (t < HD) sq[t] = q2[b * H_ + h * HD + t];
    __syncthreads();

    for (int j = t; j < L1; j += 256) {
        const float* kr = k2 + ((size_t)(b * L1 + j)) * H_ + h * HD;
        float s = 0.f;
#pragma unroll
        for (int d2 = 0; d2 < HD; d2++) s += sq[d2] * kr[d2];
        scs[j] = s * 0.17677669529663687f;
    }
    __syncthreads();

    float m = -3.4e38f;
    for (int j = t; j < L1; j += 256) m = fmaxf(m, scs[j]);
    red[t] = m;
    __syncthreads();
    for (int s = 128; s > 0; s >>= 1) { if (t < s) red[t] = fmaxf(red[t], red[t + s]); __syncthreads(); }
    m = red[0];
    __syncthreads();

    float sum = 0.f;
    for (int j = t; j < L1; j += 256) { float e = expf(scs[j] - m); scs[j] = e; sum += e; }
    red[t] = sum;
    __syncthreads();
    for (int s = 128; s > 0; s >>= 1) { if (t < s) red[t] += red[t + s]; __syncthreads(); }
    float inv = 1.f / red[0];
    __syncthreads();

    if (t < HD) {
        float acc = 0.f;
        for (int j = 0; j < L1; j++)
            acc += scs[j] * v2[((size_t)(b * L1 + j)) * H_ + h * HD + t];
        att2[b * H_ + h * HD + t] = acc * inv;
    }
}

// ---------------- final: rep = 0.5*max_l(nodes) + 0.5*relay ------------------
__global__ void final_k(const float* __restrict__ nodes, const float* __restrict__ relay,
                        float* __restrict__ out)
{
    int b = blockIdx.x, d = threadIdx.x;
    float m = -3.4e38f;
    for (int l = 0; l < L_; l++)
        m = fmaxf(m, nodes[((size_t)(b * L_ + l)) * H_ + d]);
    out[b * H_ + d] = 0.5f * m + 0.5f * relay[b * H_ + d];
}

// ---------------- host ----------------
template <typename T>
static float* sym_addr(T& sym)
{
    void* p = nullptr;
    cudaGetSymbolAddress(&p, sym);
    return (float*)p;
}

extern "C" void kernel_launch(void* const* d_in, const int* in_sizes, int n_in,
                              void* d_out, int out_size)
{
    const int*   data = (const int*)d_in[0];
    const float* emb  = (const float*)d_in[1];
    const float* fcW  = (const float*)d_in[2];
    const float* fcb  = (const float*)d_in[3];
    const float* pos  = (const float*)d_in[4];
    const float* lng  = (const float*)d_in[5];
    const float* lnb  = (const float*)d_in[6];
    const float* rWQ = (const float*)d_in[7],  *rbQ = (const float*)d_in[8];
    const float* rWK = (const float*)d_in[9],  *rbK = (const float*)d_in[10];
    const float* rWV = (const float*)d_in[11], *rbV = (const float*)d_in[12];
    const float* rWO = (const float*)d_in[13], *rbO = (const float*)d_in[14];
    const float* sWQ = (const float*)d_in[15], *sbQ = (const float*)d_in[16];
    const float* sWK = (const float*)d_in[17], *sbK = (const float*)d_in[18];
    const float* sWV = (const float*)d_in[19], *sbV = (const float*)d_in[20];
    const float* sWO = (const float*)d_in[21], *sbO = (const float*)d_in[22];
    float* out = (float*)d_out;

    float* e     = sym_addr(d_e);
    float* nodes = sym_addr(d_nodes);
    float* nln   = sym_addr(d_nln);
    float* q     = sym_addr(d_q);
    float* kbuf  = sym_addr(d_k);
    float* att   = sym_addr(d_att);
    float* y     = sym_addr(d_y);
    float* k2    = sym_addr(d_k2);
    float* v2    = sym_addr(d_v2);
    float* relay = sym_addr(d_relay);
    float* ak    = sym_addr(d_ak);
    float* av    = sym_addr(d_av);
    float* q2    = sym_addr(d_q2);
    float* att2  = sym_addr(d_att2);

    // x0 = emb[data] @ fcW + fcb + pos
    gather_emb<<<(M1 * E_ + 255) / 256, 256>>>(data, emb, e);
    {
        dim3 g((M1 + GBM - 1) / GBM, GN / GBN);
        gemm256<2><<<g, 256>>>(e, fcW, fcb, nodes, M1, E_, pos);
    }
    mean_k<<<B_, 256>>>(nodes, relay);

    dim3 g1((M1 + GBM - 1) / GBM, GN / GBN);
    dim3 g2((M2 + GBM - 1) / GBM, GN / GBN);

    for (int i = 0; i < NITER; i++) {
        const size_t wo = (size_t)i * H_ * H_;
        const size_t bo = (size_t)i * H_;

        ln_k<<<M1, 256>>>(nodes, lng + bo, lnb + bo, nln);
        gemm256<0><<<g1, 256>>>(nln, rWQ + wo, rbQ + bo, q,    M1, H_, nullptr);
        gemm256<0><<<g1, 256>>>(nln, rWK + wo, rbK + bo, kbuf, M1, H_, nullptr);
        small_proj<<<B_, 256>>>(relay, rWK + wo, rbK + bo, ak, 0);
        small_proj<<<B_, 256>>>(relay, rWV + wo, rbV + bo, av, 0);
        msa1_attn<<<M1, 256>>>(q, kbuf, ak, av, att);
        gemm256<1><<<g1, 256>>>(att, rWO + wo, rbO + bo, nodes, M1, H_, nullptr);

        ybuild<<<M2, 256>>>(relay, nodes, y, data);
        gemm256<0><<<g2, 256>>>(y, sWK + wo, sbK + bo, k2, M2, H_, nullptr);
        gemm256<0><<<g2, 256>>>(y, sWV + wo, sbV + bo, v2, M2, H_, nullptr);
        small_proj<<<B_, 256>>>(relay, sWQ + wo, sbQ + bo, q2, 0);
        msa2_attn<<<B_ * NH, 256>>>(q2, k2, v2, att2);
        small_proj<<<B_, 256>>>(att2, sWO + wo, sbO + bo, relay, 1);
    }

    final_k<<<B_, 256>>>(nodes, relay, out);
}

// round 3
// speedup vs baseline: 2.4497x; 2.4497x over previous
#include <cuda_runtime.h>
#include <math.h>
#include <stdint.h>

#define B_    32
#define L_    512
#define H_    256
#define E_    300
#define NH    8
#define HD    32
#define NITER 6
#define L1    513            // L+1 (relay + nodes)
#define M1    (B_*L_)        // 16384
#define M2    (B_*L1)        // 16416

// ---------------- scratch (static __device__, no allocation) ----------------
__device__ float d_e    [M1*E_];
__device__ float d_nodes[M1*H_];
__device__ float d_nln  [M1*H_];
__device__ float d_q    [M1*H_];
__device__ float d_k    [M1*H_];
__device__ float d_att  [M1*H_];
__device__ float d_y    [M2*H_];
__device__ float d_k2   [M2*H_];
__device__ float d_v2   [M2*H_];
__device__ float d_relay[B_*H_];
__device__ float d_ak   [B_*H_];
__device__ float d_av   [B_*H_];
__device__ float d_q2   [B_*H_];
__device__ float d_att2 [B_*H_];

// =====================================================================
// TF32 tensor-core GEMM:  C[M,256] = A[M,256] @ W[256,256]  (+ epilogue)
// EPI 0: C = acc + bias
// EPI 1: C = C + leaky_relu(acc + bias)
// =====================================================================
#define TBM 128
#define TBN 128
#define TBK 32
#define TKK 256

__device__ __forceinline__ uint32_t f2tf32(float x) {
    uint32_t r;
    asm("cvt.rna.tf32.f32 %0, %1;" : "=r"(r) : "f"(x));
    return r;
}

__device__ __forceinline__ void mma_tf32(float c[4],
                                         uint32_t a0, uint32_t a1, uint32_t a2, uint32_t a3,
                                         uint32_t b0, uint32_t b1)
{
    asm volatile(
        "mma.sync.aligned.m16n8k8.row.col.f32.tf32.tf32.f32 "
        "{%0,%1,%2,%3}, {%4,%5,%6,%7}, {%8,%9}, {%0,%1,%2,%3};"
        : "+f"(c[0]), "+f"(c[1]), "+f"(c[2]), "+f"(c[3])
        : "r"(a0), "r"(a1), "r"(a2), "r"(a3), "r"(b0), "r"(b1));
}

template<int EPI>
__global__ void __launch_bounds__(256, 2)
gemm_tf32(const float* __restrict__ A, const float* __restrict__ W,
          const float* __restrict__ bias, float* __restrict__ C, int M)
{
    __shared__ float As[TBM][TBK + 4];   // stride 36: conflict-free frag loads
    __shared__ float Bs[TBK][TBN + 8];   // stride 136

    const int tid  = threadIdx.x;
    const int m0   = blockIdx.x * TBM;
    const int n0   = blockIdx.y * TBN;
    const int warp = tid >> 5;
    const int lane = tid & 31;
    const int gid  = lane >> 2;          // 0..7
    const int tig  = lane & 3;           // 0..3
    const int warpM = warp >> 2;         // 0..1 -> m offset *64
    const int warpN = warp & 3;          // 0..3 -> n offset *32

    float acc[4][4][4];
#pragma unroll
    for (int i = 0; i < 4; i++)
#pragma unroll
        for (int j = 0; j < 4; j++)
#pragma unroll
            for (int r = 0; r < 4; r++) acc[i][j][r] = 0.f;

    for (int kb = 0; kb < TKK; kb += TBK) {
        // ---- A tile: 128x32 (row guarded), cvt to tf32 on store ----
#pragma unroll
        for (int p = 0; p < 4; p++) {
            int i = tid + p * 256;
            int r = i >> 3;
            int c = (i & 7) * 4;
            int gm = m0 + r;
            float4 v = make_float4(0.f, 0.f, 0.f, 0.f);
            if (gm < M) v = *(const float4*)(A + (size_t)gm * TKK + kb + c);
            As[r][c + 0] = __uint_as_float(f2tf32(v.x));
            As[r][c + 1] = __uint_as_float(f2tf32(v.y));
            As[r][c + 2] = __uint_as_float(f2tf32(v.z));
            As[r][c + 3] = __uint_as_float(f2tf32(v.w));
        }
        // ---- B tile: 32x128 (always in-bounds: W is 256x256) ----
#pragma unroll
        for (int p = 0; p < 4; p++) {
            int i = tid + p * 256;
            int r = i >> 5;
            int c = (i & 31) * 4;
            float4 v = *(const float4*)(W + (size_t)(kb + r) * H_ + n0 + c);
            Bs[r][c + 0] = __uint_as_float(f2tf32(v.x));
            Bs[r][c + 1] = __uint_as_float(f2tf32(v.y));
            Bs[r][c + 2] = __uint_as_float(f2tf32(v.z));
            Bs[r][c + 3] = __uint_as_float(f2tf32(v.w));
        }
        __syncthreads();

#pragma unroll
        for (int ks = 0; ks < 4; ks++) {
            const int k0 = ks * 8;
            uint32_t bf0[4], bf1[4];
#pragma unroll
            for (int nf = 0; nf < 4; nf++) {
                int cb = warpN * 32 + nf * 8 + gid;
                bf0[nf] = __float_as_uint(Bs[k0 + tig][cb]);
                bf1[nf] = __float_as_uint(Bs[k0 + tig + 4][cb]);
            }
#pragma unroll
            for (int mf = 0; mf < 4; mf++) {
                int rb = warpM * 64 + mf * 16;
                uint32_t a0 = __float_as_uint(As[rb + gid][k0 + tig]);
                uint32_t a1 = __float_as_uint(As[rb + gid + 8][k0 + tig]);
                uint32_t a2 = __float_as_uint(As[rb + gid][k0 + tig + 4]);
                uint32_t a3 = __float_as_uint(As[rb + gid + 8][k0 + tig + 4]);
#pragma unroll
                for (int nf = 0; nf < 4; nf++)
                    mma_tf32(acc[mf][nf], a0, a1, a2, a3, bf0[nf], bf1[nf]);
            }
        }
        __syncthreads();
    }

    // ---- epilogue ----
#pragma unroll
    for (int mf = 0; mf < 4; mf++) {
        int r0i = m0 + warpM * 64 + mf * 16 + gid;
        int r1i = r0i + 8;
#pragma unroll
        for (int nf = 0; nf < 4; nf++) {
            int col = n0 + warpN * 32 + nf * 8 + tig * 2;
            float2 bv = *(const float2*)(bias + col);
            float x0 = acc[mf][nf][0] + bv.x;
            float x1 = acc[mf][nf][1] + bv.y;
            float x2 = acc[mf][nf][2] + bv.x;
            float x3 = acc[mf][nf][3] + bv.y;
            if (EPI == 1) {
                x0 = x0 > 0.f ? x0 : 0.01f * x0;
                x1 = x1 > 0.f ? x1 : 0.01f * x1;
                x2 = x2 > 0.f ? x2 : 0.01f * x2;
                x3 = x3 > 0.f ? x3 : 0.01f * x3;
            }
            if (r0i < M) {
                float* p = C + (size_t)r0i * H_ + col;
                if (EPI == 1) {
                    float2 old = *(const float2*)p;
                    *(float2*)p = make_float2(old.x + x0, old.y + x1);
                } else {
                    *(float2*)p = make_float2(x0, x1);
                }
            }
            if (r1i < M) {
                float* p = C + (size_t)r1i * H_ + col;
                if (EPI == 1) {
                    float2 old = *(const float2*)p;
                    *(float2*)p = make_float2(old.x + x2, old.y + x3);
                } else {
                    *(float2*)p = make_float2(x2, x3);
                }
            }
        }
    }
}

// =====================================================================
// fp32 SIMT GEMM (kept only for the K=300 embedding GEMM, EPI 2)
// =====================================================================
#define GBM 128
#define GBN 64
#define GBK 16
#define GN  256

__global__ void __launch_bounds__(256)
gemm256_emb(const float* __restrict__ A, const float* __restrict__ W,
            const float* __restrict__ bias, float* __restrict__ C,
            int M, int K, const float* __restrict__ pos)
{
    __shared__ float As[GBK][GBM];
    __shared__ float Bs[GBK][GBN];

    const int tid = threadIdx.x;
    const int m0 = blockIdx.x * GBM;
    const int n0 = blockIdx.y * GBN;

    const int arow = tid >> 2;
    const int acol = (tid & 3) * 4;
    const int brow = tid >> 4;
    const int bcol = (tid & 15) * 4;
    const int ty = tid >> 4;
    const int tx = tid & 15;

    float acc[8][4];
#pragma unroll
    for (int i = 0; i < 8; i++)
#pragma unroll
        for (int j = 0; j < 4; j++) acc[i][j] = 0.f;

    for (int kb = 0; kb < K; kb += GBK) {
#pragma unroll
        for (int p = 0; p < 2; p++) {
            int r  = arow + p * 64;
            int gm = m0 + r;
            float4 v = make_float4(0.f, 0.f, 0.f, 0.f);
            if (gm < M) {
                int gk = kb + acol;
                if (gk + 3 < K) {
                    v = *(const float4*)(A + (size_t)gm * K + gk);
                } else {
                    float tmp[4] = {0.f, 0.f, 0.f, 0.f};
                    for (int c = 0; c < 4; c++)
                        if (gk + c < K) tmp[c] = A[(size_t)gm * K + gk + c];
                    v = make_float4(tmp[0], tmp[1], tmp[2], tmp[3]);
                }
            }
            As[acol + 0][r] = v.x;
            As[acol + 1][r] = v.y;
            As[acol + 2][r] = v.z;
            As[acol + 3][r] = v.w;
        }
        {
            int gk = kb + brow;
            float4 v = make_float4(0.f, 0.f, 0.f, 0.f);
            if (gk < K) v = *(const float4*)(W + (size_t)gk * GN + n0 + bcol);
            Bs[brow][bcol + 0] = v.x;
            Bs[brow][bcol + 1] = v.y;
            Bs[brow][bcol + 2] = v.z;
            Bs[brow][bcol + 3] = v.w;
        }
        __syncthreads();
#pragma unroll
        for (int kk = 0; kk < GBK; kk++) {
            const float* ap = &As[kk][ty * 8];
            float4 a0 = *(const float4*)ap;
            float4 a1 = *(const float4*)(ap + 4);
            float4 bb = *(const float4*)&Bs[kk][tx * 4];
            float av8[8] = {a0.x, a0.y, a0.z, a0.w, a1.x, a1.y, a1.z, a1.w};
            float bv4[4] = {bb.x, bb.y, bb.z, bb.w};
#pragma unroll
            for (int i = 0; i < 8; i++)
#pragma unroll
                for (int j = 0; j < 4; j++)
                    acc[i][j] += av8[i] * bv4[j];
        }
        __syncthreads();
    }

    float4 bv = *(const float4*)(bias + n0 + tx * 4);
#pragma unroll
    for (int i = 0; i < 8; i++) {
        int gm = m0 + ty * 8 + i;
        if (gm >= M) continue;
        const float4 p = *(const float4*)(pos + (size_t)(gm & (L_ - 1)) * GN + n0 + tx * 4);
        float* cp = C + (size_t)gm * GN + n0 + tx * 4;
        *(float4*)cp = make_float4(acc[i][0] + bv.x + p.x, acc[i][1] + bv.y + p.y,
                                   acc[i][2] + bv.z + p.z, acc[i][3] + bv.w + p.w);
    }
}

// ---------------- embedding gather ----------------
__global__ void gather_emb(const int* __restrict__ data, const float* __restrict__ emb,
                           float* __restrict__ e)
{
    size_t i = (size_t)blockIdx.x * 256 + threadIdx.x;
    if (i >= (size_t)M1 * E_) return;
    int row = (int)(i / E_);
    int c   = (int)(i % E_);
    e[i] = emb[(size_t)data[row] * E_ + c];
}

// ---------------- relay init: mean over L ----------------
__global__ void mean_k(const float* __restrict__ x, float* __restrict__ relay)
{
    int b = blockIdx.x, d = threadIdx.x;
    float acc = 0.f;
    for (int l = 0; l < L_; l++)
        acc += x[((size_t)(b * L_ + l)) * H_ + d];
    relay[b * H_ + d] = acc * (1.f / L_);
}

// ---------------- layernorm: warp per token, float4 I/O ----------------
__global__ void ln_k(const float* __restrict__ x, const float* __restrict__ g,
                     const float* __restrict__ b, float* __restrict__ y)
{
    int warp = threadIdx.x >> 5, lane = threadIdx.x & 31;
    int tok = blockIdx.x * 8 + warp;
    const float* xr = x + (size_t)tok * H_;
    float4 v0 = *(const float4*)(xr + lane * 8);
    float4 v1 = *(const float4*)(xr + lane * 8 + 4);

    float s = v0.x + v0.y + v0.z + v0.w + v1.x + v1.y + v1.z + v1.w;
#pragma unroll
    for (int o = 16; o; o >>= 1) s += __shfl_xor_sync(0xffffffffu, s, o);
    float mu = s * (1.f / H_);

    float dx[8] = {v0.x - mu, v0.y - mu, v0.z - mu, v0.w - mu,
                   v1.x - mu, v1.y - mu, v1.z - mu, v1.w - mu};
    float q = 0.f;
#pragma unroll
    for (int i = 0; i < 8; i++) q += dx[i] * dx[i];
#pragma unroll
    for (int o = 16; o; o >>= 1) q += __shfl_xor_sync(0xffffffffu, q, o);
    float rs = rsqrtf(q * (1.f / H_) + 1e-5f);

    float4 g0 = *(const float4*)(g + lane * 8);
    float4 g1 = *(const float4*)(g + lane * 8 + 4);
    float4 b0 = *(const float4*)(b + lane * 8);
    float4 b1 = *(const float4*)(b + lane * 8 + 4);
    float* yr = y + (size_t)tok * H_;
    *(float4*)(yr + lane * 8) = make_float4(
        g0.x * dx[0] * rs + b0.x, g0.y * dx[1] * rs + b0.y,
        g0.z * dx[2] * rs + b0.z, g0.w * dx[3] * rs + b0.w);
    *(float4*)(yr + lane * 8 + 4) = make_float4(
        g1.x * dx[4] * rs + b1.x, g1.y * dx[5] * rs + b1.y,
        g1.z * dx[6] * rs + b1.z, g1.w * dx[7] * rs + b1.w);
}

// ---------------- small row GEMM: C[32,256]=A[32,256]@W + b ----------
__global__ void __launch_bounds__(1024)
small_proj(const float* __restrict__ A, const float* __restrict__ W,
           const float* __restrict__ bias, float* __restrict__ C, int leaky)
{
    __shared__ float sa[H_];
    __shared__ float part[4][H_];
    int m = blockIdx.x;
    int n = threadIdx.x & 255;
    int ks = threadIdx.x >> 8;        // 0..3
    if (threadIdx.x < H_) sa[threadIdx.x] = A[(size_t)m * H_ + threadIdx.x];
    __syncthreads();
    float acc = 0.f;
    int k0 = ks * 64;
#pragma unroll 8
    for (int k = k0; k < k0 + 64; k++) acc += sa[k] * W[(size_t)k * H_ + n];
    part[ks][n] = acc;
    __syncthreads();
    if (ks == 0) {
        float r = part[0][n] + part[1][n] + part[2][n] + part[3][n] + bias[n];
        if (leaky) r = r > 0.f ? r : 0.01f * r;
        C[(size_t)m * H_ + n] = r;
    }
}

// ---------------- ring attention (msa1) ----------------
__global__ void msa1_attn(const float* __restrict__ q, const float* __restrict__ k,
                          const float* __restrict__ ak, const float* __restrict__ av,
                          float* __restrict__ att)
{
    int token = blockIdx.x;
    int b = token >> 9;
    int l = token & 511;
    int h = threadIdx.x >> 5;
    int d = threadIdx.x & 31;
    int off = h * HD + d;

    float qd  = q[(size_t)token * H_ + off];
    float akd = ak[b * H_ + off];
    float avd = av[b * H_ + off];
    float km1 = (l > 0)      ? k[(size_t)(token - 1) * H_ + off] : 0.f;
    float k0v =                k[(size_t)token * H_ + off];
    float kp1 = (l < L_ - 1) ? k[(size_t)(token + 1) * H_ + off] : 0.f;

    float s0 = qd * akd, s1 = qd * km1, s2 = qd * k0v, s3 = qd * kp1;
#pragma unroll
    for (int o = 16; o; o >>= 1) {
        s0 += __shfl_xor_sync(0xffffffffu, s0, o);
        s1 += __shfl_xor_sync(0xffffffffu, s1, o);
        s2 += __shfl_xor_sync(0xffffffffu, s2, o);
        s3 += __shfl_xor_sync(0xffffffffu, s3, o);
    }
    const float sc = 0.17677669529663687f;
    s0 *= sc; s1 *= sc; s2 *= sc; s3 *= sc;
    float mx = fmaxf(fmaxf(s0, s1), fmaxf(s2, s3));
    float e0 = expf(s0 - mx), e1 = expf(s1 - mx), e2 = expf(s2 - mx), e3 = expf(s3 - mx);
    float inv = 1.f / (e0 + e1 + e2 + e3);
    att[(size_t)token * H_ + off] = (e0 * avd + e1 * km1 + e2 * k0v + e3 * kp1) * inv;
}

// ---------------- build y = [relay; nodes], mask nodes after ----------------
__global__ void ybuild(const float* __restrict__ relay, float* __restrict__ nodes,
                       float* __restrict__ y, const int* __restrict__ data)
{
    int row = blockIdx.x;
    int d = threadIdx.x;
    int b = row / L1;
    int j = row - b * L1;
    if (j == 0) {
        y[(size_t)row * H_ + d] = relay[b * H_ + d];
    } else {
        int tok = b * L_ + (j - 1);
        float v = nodes[(size_t)tok * H_ + d];
        y[(size_t)row * H_ + d] = v;
        if (data[tok] == 1) nodes[(size_t)tok * H_ + d] = 0.f;
    }
}

// ---------------- relay attention (msa2) ----------------
__global__ void msa2_attn(const float* __restrict__ q2, const float* __restrict__ k2,
                          const float* __restrict__ v2, float* __restrict__ att2)
{
    __shared__ float sq[HD];
    __shared__ float scs[L1];
    __shared__ float red[256];
    __shared__ float part[8][HD];
    int bh = blockIdx.x;
    int b = bh >> 3, h = bh & 7;
    int t = threadIdx.x;

    if (t < HD) sq[t] = q2[b * H_ + h * HD + t];
    __syncthreads();

    for (int j = t; j < L1; j += 256) {
        const float* kr = k2 + ((size_t)(b * L1 + j)) * H_ + h * HD;
        float s = 0.f;
#pragma unroll
        for (int d2 = 0; d2 < HD; d2++) s += sq[d2] * kr[d2];
        scs[j] = s * 0.17677669529663687f;
    }
    __syncthreads();

    float m = -3.4e38f;
    for (int j = t; j < L1; j += 256) m = fmaxf(m, scs[j]);
    red[t] = m;
    __syncthreads();
    for (int s = 128; s > 0; s >>= 1) { if (t < s) red[t] = fmaxf(red[t], red[t + s]); __syncthreads(); }
    m = red[0];
    __syncthreads();

    float sum = 0.f;
    for (int j = t; j < L1; j += 256) { float e = expf(scs[j] - m); scs[j] = e; sum += e; }
    red[t] = sum;
    __syncthreads();
    for (int s = 128; s > 0; s >>= 1) { if (t < s) red[t] += red[t + s]; __syncthreads(); }
    float inv = 1.f / red[0];
    __syncthreads();

    // weighted V: 8 warps split the j range, then reduce
    int jg = t >> 5, d = t & 31;
    float acc = 0.f;
    for (int j = jg; j < L1; j += 8)
        acc += scs[j] * v2[((size_t)(b * L1 + j)) * H_ + h * HD + d];
    part[jg][d] = acc;
    __syncthreads();
    if (t < HD) {
        float s = 0.f;
#pragma unroll
        for (int g2 = 0; g2 < 8; g2++) s += part[g2][t];
        att2[b * H_ + h * HD + t] = s * inv;
    }
}

// ---------------- final: rep = 0.5*max_l(nodes) + 0.5*relay ------------------
__global__ void final_k(const float* __restrict__ nodes, const float* __restrict__ relay,
                        float* __restrict__ out)
{
    int b = blockIdx.x, d = threadIdx.x;
    float m = -3.4e38f;
    for (int l = 0; l < L_; l++)
        m = fmaxf(m, nodes[((size_t)(b * L_ + l)) * H_ + d]);
    out[b * H_ + d] = 0.5f * m + 0.5f * relay[b * H_ + d];
}

// ---------------- host ----------------
template <typename T>
static float* sym_addr(T& sym)
{
    void* p = nullptr;
    cudaGetSymbolAddress(&p, sym);
    return (float*)p;
}

extern "C" void kernel_launch(void* const* d_in, const int* in_sizes, int n_in,
                              void* d_out, int out_size)
{
    const int*   data = (const int*)d_in[0];
    const float* emb  = (const float*)d_in[1];
    const float* fcW  = (const float*)d_in[2];
    const float* fcb  = (const float*)d_in[3];
    const float* pos  = (const float*)d_in[4];
    const float* lng  = (const float*)d_in[5];
    const float* lnb  = (const float*)d_in[6];
    const float* rWQ = (const float*)d_in[7],  *rbQ = (const float*)d_in[8];
    const float* rWK = (const float*)d_in[9],  *rbK = (const float*)d_in[10];
    const float* rWV = (const float*)d_in[11], *rbV = (const float*)d_in[12];
    const float* rWO = (const float*)d_in[13], *rbO = (const float*)d_in[14];
    const float* sWQ = (const float*)d_in[15], *sbQ = (const float*)d_in[16];
    const float* sWK = (const float*)d_in[17], *sbK = (const float*)d_in[18];
    const float* sWV = (const float*)d_in[19], *sbV = (const float*)d_in[20];
    const float* sWO = (const float*)d_in[21], *sbO = (const float*)d_in[22];
    float* out = (float*)d_out;

    float* e     = sym_addr(d_e);
    float* nodes = sym_addr(d_nodes);
    float* nln   = sym_addr(d_nln);
    float* q     = sym_addr(d_q);
    float* kbuf  = sym_addr(d_k);
    float* att   = sym_addr(d_att);
    float* y     = sym_addr(d_y);
    float* k2    = sym_addr(d_k2);
    float* v2    = sym_addr(d_v2);
    float* relay = sym_addr(d_relay);
    float* ak    = sym_addr(d_ak);
    float* av    = sym_addr(d_av);
    float* q2    = sym_addr(d_q2);
    float* att2  = sym_addr(d_att2);

    // x0 = emb[data] @ fcW + fcb + pos
    gather_emb<<<(M1 * E_ + 255) / 256, 256>>>(data, emb, e);
    {
        dim3 g((M1 + GBM - 1) / GBM, GN / GBN);
        gemm256_emb<<<g, 256>>>(e, fcW, fcb, nodes, M1, E_, pos);
    }
    mean_k<<<B_, 256>>>(nodes, relay);

    dim3 t1(M1 / TBM, H_ / TBN);                  // 128 x 2
    dim3 t2((M2 + TBM - 1) / TBM, H_ / TBN);      // 129 x 2

    for (int i = 0; i < NITER; i++) {
        const size_t wo = (size_t)i * H_ * H_;
        const size_t bo = (size_t)i * H_;

        ln_k<<<M1 / 8, 256>>>(nodes, lng + bo, lnb + bo, nln);
        gemm_tf32<0><<<t1, 256>>>(nln, rWQ + wo, rbQ + bo, q,    M1);
        gemm_tf32<0><<<t1, 256>>>(nln, rWK + wo, rbK + bo, kbuf, M1);
        small_proj<<<B_, 1024>>>(relay, rWK + wo, rbK + bo, ak, 0);
        small_proj<<<B_, 1024>>>(relay, rWV + wo, rbV + bo, av, 0);
        msa1_attn<<<M1, 256>>>(q, kbuf, ak, av, att);
        gemm_tf32<1><<<t1, 256>>>(att, rWO + wo, rbO + bo, nodes, M1);

        ybuild<<<M2, 256>>>(relay, nodes, y, data);
        gemm_tf32<0><<<t2, 256>>>(y, sWK + wo, sbK + bo, k2, M2);
        gemm_tf32<0><<<t2, 256>>>(y, sWV + wo, sbV + bo, v2, M2);
        small_proj<<<B_, 1024>>>(relay, sWQ + wo, sbQ + bo, q2, 0);
        msa2_attn<<<B_ * NH, 256>>>(q2, k2, v2, att2);
        small_proj<<<B_, 1024>>>(att2, sWO + wo, sbO + bo, relay, 1);
    }

    final_k<<<B_, 256>>>(nodes, relay, out);
}

// round 4
// speedup vs baseline: 3.0422x; 1.2419x over previous
#include <cuda_runtime.h>
#include <math.h>
#include <stdint.h>

#define B_    32
#define L_    512
#define H_    256
#define E_    300
#define NH    8
#define HD    32
#define NITER 6
#define L1    513
#define M1    (B_*L_)        // 16384
#define M2    (B_*L1)        // 16416

// ---------------- scratch ----------------
__device__ float d_nodes[M1*H_];
__device__ float d_u    [M1*H_];     // unmasked nodes (also reused as nln)
__device__ float d_q    [M1*H_];
__device__ float d_k    [M1*H_];
__device__ float d_att  [M1*H_];
__device__ float d_k2   [M2*H_];
__device__ float d_v2   [M2*H_];
__device__ float d_relay[B_*H_];
__device__ float d_ak   [B_*H_];
__device__ float d_av   [B_*H_];
__device__ float d_q2   [B_*H_];
__device__ float d_att2 [B_*H_];
__device__ float d_part [B_*16*H_];

// =====================================================================
// Unified TF32 tensor-core GEMM, cp.async double-buffered.
// MODE 0 (QK): dual output, A direct, plain epilogue
// MODE 1 (O):  single, u = nodes + leaky(acc+b); write u and masked nodes
// MODE 2 (KV): dual output, row-remap r -> r + r/512 + 1
// MODE 3 (EMB): single, A gathered from emb[data[r]], K=300, +pos epilogue
// =====================================================================
#define TBM 128
#define TBN 128
#define TBK 32
#define ASTR 36
#define GEMM_SMEM ((2*TBM*ASTR + 2*TBK*TBN)*4)   // 69632 bytes

__device__ __forceinline__ uint32_t f2tf32(float x) {
    uint32_t r;
    asm("cvt.rna.tf32.f32 %0, %1;" : "=r"(r) : "f"(x));
    return r;
}

__device__ __forceinline__ void mma_tf32(float c[4],
                                         uint32_t a0, uint32_t a1, uint32_t a2, uint32_t a3,
                                         uint32_t b0, uint32_t b1)
{
    asm volatile(
        "mma.sync.aligned.m16n8k8.row.col.f32.tf32.tf32.f32 "
        "{%0,%1,%2,%3}, {%4,%5,%6,%7}, {%8,%9}, {%0,%1,%2,%3};"
        : "+f"(c[0]), "+f"(c[1]), "+f"(c[2]), "+f"(c[3])
        : "r"(a0), "r"(a1), "r"(a2), "r"(a3), "r"(b0), "r"(b1));
}

__device__ __forceinline__ void cpa16(uint32_t dst, const void* src, bool ok) {
    int sz = ok ? 16 : 0;
    asm volatile("cp.async.cg.shared.global [%0], [%1], 16, %2;"
                 :: "r"(dst), "l"(src), "r"(sz));
}

template<int MODE>
__global__ void __launch_bounds__(256, 2)
gemm_uni(const float* __restrict__ A,
         const float* __restrict__ W1, const float* __restrict__ b1, float* __restrict__ C1,
         const float* __restrict__ W2, const float* __restrict__ b2, float* __restrict__ C2,
         const float* __restrict__ pos, const int* __restrict__ tok,
         const float* __restrict__ emb, float* __restrict__ uOut,
         float* __restrict__ nodes)
{
    constexpr int  K    = (MODE == 3) ? 300 : 256;
    constexpr int  NKT  = (K + TBK - 1) / TBK;
    constexpr bool DUAL = (MODE == 0 || MODE == 2);

    extern __shared__ float smraw[];
    float* As = smraw;
    float* Bs = smraw + 2 * TBM * ASTR;
    uint32_t aS = (uint32_t)__cvta_generic_to_shared(As);
    uint32_t bS = (uint32_t)__cvta_generic_to_shared(Bs);

    const int tid = threadIdx.x;
    const int m0  = blockIdx.x * TBM;

    const float *W, *bias; float* C;
    int n0;
    if (DUAL) {
        bool sec = (blockIdx.y >> 1);
        W = sec ? W2 : W1; bias = sec ? b2 : b1; C = sec ? C2 : C1;
        n0 = (blockIdx.y & 1) * TBN;
    } else {
        W = W1; bias = b1; C = C1;
        n0 = blockIdx.y * TBN;
    }

    // per-thread load slots (4 x 16B for A, 4 x 16B for B)
    const float* aSrc[4]; uint32_t aDst[4]; int aCC[4];
    const float* bSrc[4]; uint32_t bDst[4]; int bR[4];
#pragma unroll
    for (int p = 0; p < 4; p++) {
        int j = tid + p * 256;
        int r = j >> 3, cc = (j & 7) * 4;
        if (MODE == 3) aSrc[p] = emb + (size_t)__ldg(tok + m0 + r) * E_ + cc;
        else           aSrc[p] = A + (size_t)(m0 + r) * 256 + cc;
        aDst[p] = aS + (uint32_t)(r * ASTR + cc) * 4;
        aCC[p]  = cc;
        int rb = j >> 5, cb = (j & 31) * 4;
        bSrc[p] = W + (size_t)rb * 256 + n0 + cb;
        bDst[p] = bS + (uint32_t)(rb * TBN + (cb ^ (8 * (rb & 3)))) * 4;
        bR[p]   = rb;
    }

    const int warp = tid >> 5, lane = tid & 31;
    const int gid = lane >> 2, tig = lane & 3;
    const int warpM = warp >> 2, warpN = warp & 3;

    float acc[4][4][4];
#pragma unroll
    for (int i = 0; i < 4; i++)
#pragma unroll
        for (int j = 0; j < 4; j++)
#pragma unroll
            for (int r = 0; r < 4; r++) acc[i][j][r] = 0.f;

    const uint32_t aBufB = TBM * ASTR * 4;
    const uint32_t bBufB = TBK * TBN * 4;

    // prologue: tile 0
#pragma unroll
    for (int p = 0; p < 4; p++) {
        cpa16(aDst[p], aSrc[p], true);
        cpa16(bDst[p], bSrc[p], true);
    }
    asm volatile("cp.async.commit_group;");

    for (int kb = 0; kb < NKT; kb++) {
        int kn = (kb + 1) * TBK;
        if (kb + 1 < NKT) {
            uint32_t aO = ((kb + 1) & 1) * aBufB;
            uint32_t bO = ((kb + 1) & 1) * bBufB;
#pragma unroll
            for (int p = 0; p < 4; p++) {
                bool okA = (MODE != 3) || (kn + aCC[p] < K);
                cpa16(aDst[p] + aO, aSrc[p] + kn, okA);
                bool okB = (MODE != 3) || (kn + bR[p] < K);
                cpa16(bDst[p] + bO, bSrc[p] + (size_t)kn * 256, okB);
            }
        }
        asm volatile("cp.async.commit_group;");
        asm volatile("cp.async.wait_group 1;");
        __syncthreads();

        const float* Ab = As + (kb & 1) * (TBM * ASTR);
        const float* Bb = Bs + (kb & 1) * (TBK * TBN);
#pragma unroll
        for (int ks = 0; ks < 4; ks++) {
            const int k0 = ks * 8;
            const int xr = 8 * tig;
            uint32_t bf0[4], bf1[4];
#pragma unroll
            for (int nf = 0; nf < 4; nf++) {
                int cb = warpN * 32 + nf * 8 + gid;
                int pc = cb ^ xr;
                bf0[nf] = f2tf32(Bb[(k0 + tig) * TBN + pc]);
                bf1[nf] = f2tf32(Bb[(k0 + tig + 4) * TBN + pc]);
            }
#pragma unroll
            for (int mf = 0; mf < 4; mf++) {
                int rb = warpM * 64 + mf * 16;
                uint32_t a0 = f2tf32(Ab[(rb + gid)     * ASTR + k0 + tig]);
                uint32_t a1 = f2tf32(Ab[(rb + gid + 8) * ASTR + k0 + tig]);
                uint32_t a2 = f2tf32(Ab[(rb + gid)     * ASTR + k0 + tig + 4]);
                uint32_t a3 = f2tf32(Ab[(rb + gid + 8) * ASTR + k0 + tig + 4]);
#pragma unroll
                for (int nf = 0; nf < 4; nf++)
                    mma_tf32(acc[mf][nf], a0, a1, a2, a3, bf0[nf], bf1[nf]);
            }
        }
        __syncthreads();
    }

    // ---- epilogue ----
#pragma unroll
    for (int mf = 0; mf < 4; mf++) {
        int r0i = m0 + warpM * 64 + mf * 16 + gid;
        int r1i = r0i + 8;
        int o0 = r0i, o1 = r1i;
        if (MODE == 2) { o0 = r0i + (r0i >> 9) + 1; o1 = r1i + (r1i >> 9) + 1; }
        int msk0 = 0, msk1 = 0;
        if (MODE == 1) { msk0 = (__ldg(tok + r0i) == 1); msk1 = (__ldg(tok + r1i) == 1); }
#pragma unroll
        for (int nf = 0; nf < 4; nf++) {
            int col = n0 + warpN * 32 + nf * 8 + tig * 2;
            float2 bv = *(const float2*)(bias + col);
            float x0 = acc[mf][nf][0] + bv.x;
            float x1 = acc[mf][nf][1] + bv.y;
            float x2 = acc[mf][nf][2] + bv.x;
            float x3 = acc[mf][nf][3] + bv.y;
            if (MODE == 3) {
                float2 p0 = *(const float2*)(pos + (size_t)(r0i & 511) * 256 + col);
                float2 p1 = *(const float2*)(pos + (size_t)(r1i & 511) * 256 + col);
                x0 += p0.x; x1 += p0.y; x2 += p1.x; x3 += p1.y;
            }
            if (MODE == 1) {
                x0 = x0 > 0.f ? x0 : 0.01f * x0;
                x1 = x1 > 0.f ? x1 : 0.01f * x1;
                x2 = x2 > 0.f ? x2 : 0.01f * x2;
                x3 = x3 > 0.f ? x3 : 0.01f * x3;
                float2 old0 = *(const float2*)(nodes + (size_t)r0i * 256 + col);
                float2 old1 = *(const float2*)(nodes + (size_t)r1i * 256 + col);
                float u0 = old0.x + x0, u1 = old0.y + x1;
                float u2 = old1.x + x2, u3 = old1.y + x3;
                *(float2*)(uOut + (size_t)r0i * 256 + col) = make_float2(u0, u1);
                *(float2*)(uOut + (size_t)r1i * 256 + col) = make_float2(u2, u3);
                *(float2*)(nodes + (size_t)r0i * 256 + col) =
                    msk0 ? make_float2(0.f, 0.f) : make_float2(u0, u1);
                *(float2*)(nodes + (size_t)r1i * 256 + col) =
                    msk1 ? make_float2(0.f, 0.f) : make_float2(u2, u3);
            } else {
                *(float2*)(C + (size_t)o0 * 256 + col) = make_float2(x0, x1);
                *(float2*)(C + (size_t)o1 * 256 + col) = make_float2(x2, x3);
            }
        }
    }
}

// ---------------- layernorm: 2 tokens per warp ----------------
__global__ void __launch_bounds__(256)
ln_k(const float* __restrict__ x, const float* __restrict__ g,
     const float* __restrict__ b, float* __restrict__ y)
{
    int warp = threadIdx.x >> 5, lane = threadIdx.x & 31;
    int t0 = (blockIdx.x * 8 + warp) * 2;
    const float* xa = x + (size_t)t0 * H_;
    const float* xb = xa + H_;
    float4 a0 = *(const float4*)(xa + lane * 8);
    float4 a1 = *(const float4*)(xa + lane * 8 + 4);
    float4 c0 = *(const float4*)(xb + lane * 8);
    float4 c1 = *(const float4*)(xb + lane * 8 + 4);

    float sA = a0.x + a0.y + a0.z + a0.w + a1.x + a1.y + a1.z + a1.w;
    float sB = c0.x + c0.y + c0.z + c0.w + c1.x + c1.y + c1.z + c1.w;
#pragma unroll
    for (int o = 16; o; o >>= 1) {
        sA += __shfl_xor_sync(0xffffffffu, sA, o);
        sB += __shfl_xor_sync(0xffffffffu, sB, o);
    }
    float muA = sA * (1.f / H_), muB = sB * (1.f / H_);

    float dA[8] = {a0.x - muA, a0.y - muA, a0.z - muA, a0.w - muA,
                   a1.x - muA, a1.y - muA, a1.z - muA, a1.w - muA};
    float dB[8] = {c0.x - muB, c0.y - muB, c0.z - muB, c0.w - muB,
                   c1.x - muB, c1.y - muB, c1.z - muB, c1.w - muB};
    float qA = 0.f, qB = 0.f;
#pragma unroll
    for (int i = 0; i < 8; i++) { qA += dA[i] * dA[i]; qB += dB[i] * dB[i]; }
#pragma unroll
    for (int o = 16; o; o >>= 1) {
        qA += __shfl_xor_sync(0xffffffffu, qA, o);
        qB += __shfl_xor_sync(0xffffffffu, qB, o);
    }
    float rA = rsqrtf(qA * (1.f / H_) + 1e-5f);
    float rB = rsqrtf(qB * (1.f / H_) + 1e-5f);

    float4 g0 = *(const float4*)(g + lane * 8);
    float4 g1 = *(const float4*)(g + lane * 8 + 4);
    float4 bb0 = *(const float4*)(b + lane * 8);
    float4 bb1 = *(const float4*)(b + lane * 8 + 4);
    float* ya = y + (size_t)t0 * H_;
    float* yb = ya + H_;
    *(float4*)(ya + lane * 8) = make_float4(
        g0.x * dA[0] * rA + bb0.x, g0.y * dA[1] * rA + bb0.y,
        g0.z * dA[2] * rA + bb0.z, g0.w * dA[3] * rA + bb0.w);
    *(float4*)(ya + lane * 8 + 4) = make_float4(
        g1.x * dA[4] * rA + bb1.x, g1.y * dA[5] * rA + bb1.y,
        g1.z * dA[6] * rA + bb1.z, g1.w * dA[7] * rA + bb1.w);
    *(float4*)(yb + lane * 8) = make_float4(
        g0.x * dB[0] * rB + bb0.x, g0.y * dB[1] * rB + bb0.y,
        g0.z * dB[2] * rB + bb0.z, g0.w * dB[3] * rB + bb0.w);
    *(float4*)(yb + lane * 8 + 4) = make_float4(
        g1.x * dB[4] * rB + bb1.x, g1.y * dB[5] * rB + bb1.y,
        g1.z * dB[6] * rB + bb1.z, g1.w * dB[7] * rB + bb1.w);
}

// ---------------- batched small row GEMMs (up to 3 outputs via gridDim.y) ----
__global__ void __launch_bounds__(1024)
small3(const float* __restrict__ A,
       const float* __restrict__ W0, const float* __restrict__ bi0, float* __restrict__ C0, int ld0,
       const float* __restrict__ W1, const float* __restrict__ bi1, float* __restrict__ C1, int ld1,
       const float* __restrict__ W2, const float* __restrict__ bi2, float* __restrict__ C2, int ld2,
       int leaky)
{
    __shared__ float sa[H_];
    __shared__ float part[4][H_];
    const float *W, *bi; float* C; int ld;
    if (blockIdx.y == 0)      { W = W0; bi = bi0; C = C0; ld = ld0; }
    else if (blockIdx.y == 1) { W = W1; bi = bi1; C = C1; ld = ld1; }
    else                      { W = W2; bi = bi2; C = C2; ld = ld2; }
    int m = blockIdx.x;
    int n = threadIdx.x & 255, ks = threadIdx.x >> 8;
    if (threadIdx.x < H_) sa[threadIdx.x] = A[(size_t)m * H_ + threadIdx.x];
    __syncthreads();
    float acc = 0.f;
    int k0 = ks * 64;
#pragma unroll 8
    for (int k = k0; k < k0 + 64; k++) acc += sa[k] * W[(size_t)k * H_ + n];
    part[ks][n] = acc;
    __syncthreads();
    if (ks == 0) {
        float r = part[0][n] + part[1][n] + part[2][n] + part[3][n] + bi[n];
        if (leaky) r = r > 0.f ? r : 0.01f * r;
        C[(size_t)m * ld + n] = r;
    }
}

// ---------------- ring attention (msa1) ----------------
__global__ void msa1_attn(const float* __restrict__ q, const float* __restrict__ k,
                          const float* __restrict__ ak, const float* __restrict__ av,
                          float* __restrict__ att)
{
    int token = blockIdx.x;
    int b = token >> 9;
    int l = token & 511;
    int h = threadIdx.x >> 5;
    int d = threadIdx.x & 31;
    int off = h * HD + d;

    float qd  = q[(size_t)token * H_ + off];
    float akd = ak[b * H_ + off];
    float avd = av[b * H_ + off];
    float km1 = (l > 0)      ? k[(size_t)(token - 1) * H_ + off] : 0.f;
    float k0v =                k[(size_t)token * H_ + off];
    float kp1 = (l < L_ - 1) ? k[(size_t)(token + 1) * H_ + off] : 0.f;

    float s0 = qd * akd, s1 = qd * km1, s2 = qd * k0v, s3 = qd * kp1;
#pragma unroll
    for (int o = 16; o; o >>= 1) {
        s0 += __shfl_xor_sync(0xffffffffu, s0, o);
        s1 += __shfl_xor_sync(0xffffffffu, s1, o);
        s2 += __shfl_xor_sync(0xffffffffu, s2, o);
        s3 += __shfl_xor_sync(0xffffffffu, s3, o);
    }
    const float sc = 0.17677669529663687f;
    s0 *= sc; s1 *= sc; s2 *= sc; s3 *= sc;
    float mx = fmaxf(fmaxf(s0, s1), fmaxf(s2, s3));
    float e0 = expf(s0 - mx), e1 = expf(s1 - mx), e2 = expf(s2 - mx), e3 = expf(s3 - mx);
    float inv = 1.f / (e0 + e1 + e2 + e3);
    att[(size_t)token * H_ + off] = (e0 * avd + e1 * km1 + e2 * k0v + e3 * kp1) * inv;
}

// ---------------- relay attention (msa2), coalesced scores ----------------
__global__ void __launch_bounds__(256)
msa2_attn(const float* __restrict__ q2, const float* __restrict__ k2,
          const float* __restrict__ v2, float* __restrict__ att2)
{
    __shared__ float sq[HD];
    __shared__ float scs[L1];
    __shared__ float red[256];
    __shared__ float part[8][HD];
    int b = blockIdx.x >> 3, h = blockIdx.x & 7;
    int t = threadIdx.x, w = t >> 5, lane = t & 31;

    if (t < HD) sq[t] = q2[b * H_ + h * HD + t];
    __syncthreads();

    for (int j = w; j < L1; j += 8) {
        float v = k2[((size_t)(b * L1 + j)) * H_ + h * HD + lane] * sq[lane];
#pragma unroll
        for (int o = 16; o; o >>= 1) v += __shfl_xor_sync(0xffffffffu, v, o);
        if (lane == 0) scs[j] = v * 0.17677669529663687f;
    }
    __syncthreads();

    float m = -3.4e38f;
    for (int j = t; j < L1; j += 256) m = fmaxf(m, scs[j]);
    red[t] = m;
    __syncthreads();
    for (int s = 128; s > 0; s >>= 1) { if (t < s) red[t] = fmaxf(red[t], red[t + s]); __syncthreads(); }
    m = red[0];
    __syncthreads();

    float sum = 0.f;
    for (int j = t; j < L1; j += 256) { float e = expf(scs[j] - m); scs[j] = e; sum += e; }
    red[t] = sum;
    __syncthreads();
    for (int s = 128; s > 0; s >>= 1) { if (t < s) red[t] += red[t + s]; __syncthreads(); }
    float inv = 1.f / red[0];
    __syncthreads();

    float acc = 0.f;
    for (int j = w; j < L1; j += 8)
        acc += scs[j] * v2[((size_t)(b * L1 + j)) * H_ + h * HD + lane];
    part[w][lane] = acc;
    __syncthreads();
    if (t < HD) {
        float s = 0.f;
#pragma unroll
        for (int g2 = 0; g2 < 8; g2++) s += part[g2][t];
        att2[b * H_ + h * HD + t] = s * inv;
    }
}

// ---------------- two-stage mean / max ----------------
__global__ void mean_part_k(const float* __restrict__ x, float* __restrict__ part)
{
    int b = blockIdx.x, c = blockIdx.y, d = threadIdx.x;
    float s = 0.f;
#pragma unroll 8
    for (int l = c * 32; l < c * 32 + 32; l++)
        s += x[((size_t)(b * L_ + l)) * H_ + d];
    part[(size_t)(b * 16 + c) * H_ + d] = s;
}
__global__ void mean_comb_k(const float* __restrict__ part, float* __restrict__ relay)
{
    int b = blockIdx.x, d = threadIdx.x;
    float s = 0.f;
#pragma unroll
    for (int c = 0; c < 16; c++) s += part[(size_t)(b * 16 + c) * H_ + d];
    relay[b * H_ + d] = s * (1.f / L_);
}
__global__ void max_part_k(const float* __restrict__ x, float* __restrict__ part)
{
    int b = blockIdx.x, c = blockIdx.y, d = threadIdx.x;
    float s = -3.4e38f;
#pragma unroll 8
    for (int l = c * 32; l < c * 32 + 32; l++)
        s = fmaxf(s, x[((size_t)(b * L_ + l)) * H_ + d]);
    part[(size_t)(b * 16 + c) * H_ + d] = s;
}
__global__ void final_comb_k(const float* __restrict__ part, const float* __restrict__ relay,
                             float* __restrict__ out)
{
    int b = blockIdx.x, d = threadIdx.x;
    float s = -3.4e38f;
#pragma unroll
    for (int c = 0; c < 16; c++) s = fmaxf(s, part[(size_t)(b * 16 + c) * H_ + d]);
    out[b * H_ + d] = 0.5f * s + 0.5f * relay[b * H_ + d];
}

// ---------------- host ----------------
template <typename T>
static float* sym_addr(T& sym)
{
    void* p = nullptr;
    cudaGetSymbolAddress(&p, sym);
    return (float*)p;
}

extern "C" void kernel_launch(void* const* d_in, const int* in_sizes, int n_in,
                              void* d_out, int out_size)
{
    const int*   data = (const int*)d_in[0];
    const float* emb  = (const float*)d_in[1];
    const float* fcW  = (const float*)d_in[2];
    const float* fcb  = (const float*)d_in[3];
    const float* pos  = (const float*)d_in[4];
    const float* lng  = (const float*)d_in[5];
    const float* lnb  = (const float*)d_in[6];
    const float* rWQ = (const float*)d_in[7],  *rbQ = (const float*)d_in[8];
    const float* rWK = (const float*)d_in[9],  *rbK = (const float*)d_in[10];
    const float* rWV = (const float*)d_in[11], *rbV = (const float*)d_in[12];
    const float* rWO = (const float*)d_in[13], *rbO = (const float*)d_in[14];
    const float* sWQ = (const float*)d_in[15], *sbQ = (const float*)d_in[16];
    const float* sWK = (const float*)d_in[17], *sbK = (const float*)d_in[18];
    const float* sWV = (const float*)d_in[19], *sbV = (const float*)d_in[20];
    const float* sWO = (const float*)d_in[21], *sbO = (const float*)d_in[22];
    float* out = (float*)d_out;

    float* nodes = sym_addr(d_nodes);
    float* u     = sym_addr(d_u);
    float* q     = sym_addr(d_q);
    float* kbuf  = sym_addr(d_k);
    float* att   = sym_addr(d_att);
    float* k2    = sym_addr(d_k2);
    float* v2    = sym_addr(d_v2);
    float* relay = sym_addr(d_relay);
    float* ak    = sym_addr(d_ak);
    float* av    = sym_addr(d_av);
    float* q2    = sym_addr(d_q2);
    float* att2  = sym_addr(d_att2);
    float* part  = sym_addr(d_part);

    cudaFuncSetAttribute(gemm_uni<0>, cudaFuncAttributeMaxDynamicSharedMemorySize, GEMM_SMEM);
    cudaFuncSetAttribute(gemm_uni<1>, cudaFuncAttributeMaxDynamicSharedMemorySize, GEMM_SMEM);
    cudaFuncSetAttribute(gemm_uni<2>, cudaFuncAttributeMaxDynamicSharedMemorySize, GEMM_SMEM);
    cudaFuncSetAttribute(gemm_uni<3>, cudaFuncAttributeMaxDynamicSharedMemorySize, GEMM_SMEM);

    const dim3 gDual(M1 / TBM, 4);
    const dim3 gSingle(M1 / TBM, 2);

    // x0 = emb[data] @ fcW + fcb + pos   (gather fused into A loader)
    gemm_uni<3><<<gSingle, 256, GEMM_SMEM>>>(nullptr, fcW, fcb, nodes,
                                             nullptr, nullptr, nullptr,
                                             pos, data, emb, nullptr, nullptr);
    mean_part_k<<<dim3(B_, 16), 256>>>(nodes, part);
    mean_comb_k<<<B_, 256>>>(part, relay);

    for (int i = 0; i < NITER; i++) {
        const size_t wo = (size_t)i * H_ * H_;
        const size_t bo = (size_t)i * H_;

        ln_k<<<M1 / 16, 256>>>(nodes, lng + bo, lnb + bo, u);   // u reused as nln
        gemm_uni<0><<<gDual, 256, GEMM_SMEM>>>(u, rWQ + wo, rbQ + bo, q,
                                               rWK + wo, rbK + bo, kbuf,
                                               nullptr, nullptr, nullptr, nullptr, nullptr);
        small3<<<dim3(B_, 2), 1024>>>(relay,
                                      rWK + wo, rbK + bo, ak, H_,
                                      rWV + wo, rbV + bo, av, H_,
                                      nullptr, nullptr, nullptr, 0, 0);
        msa1_attn<<<M1, 256>>>(q, kbuf, ak, av, att);
        gemm_uni<1><<<gSingle, 256, GEMM_SMEM>>>(att, rWO + wo, rbO + bo, nullptr,
                                                 nullptr, nullptr, nullptr,
                                                 nullptr, data, nullptr, u, nodes);

        // relay-row projections: q2, and row 0 of k2/v2 for every batch
        small3<<<dim3(B_, 3), 1024>>>(relay,
                                      sWQ + wo, sbQ + bo, q2, H_,
                                      sWK + wo, sbK + bo, k2, L1 * H_,
                                      sWV + wo, sbV + bo, v2, L1 * H_, 0);
        // node rows of k2/v2 (row remap fused into epilogue)
        gemm_uni<2><<<gDual, 256, GEMM_SMEM>>>(u, sWK + wo, sbK + bo, k2,
                                               sWV + wo, sbV + bo, v2,
                                               nullptr, nullptr, nullptr, nullptr, nullptr);
        msa2_attn<<<B_ * NH, 256>>>(q2, k2, v2, att2);
        small3<<<dim3(B_, 1), 1024>>>(att2,
                                      sWO + wo, sbO + bo, relay, H_,
                                      nullptr, nullptr, nullptr, 0,
                                      nullptr, nullptr, nullptr, 0, 1);
    }

    max_part_k<<<dim3(B_, 16), 256>>>(nodes, part);
    final_comb_k<<<B_, 256>>>(part, relay, out);
}